// round 1
// baseline (speedup 1.0000x reference)
#include <cuda_runtime.h>
#include <math.h>

// Problem shape (fixed by setup_inputs): B=8, S=2048, D=H=1024
#define DH   1024
#define BB   8
#define SS   2048
#define MM   (BB * SS)          // 16384 rows

// ---------------------------------------------------------------------------
// Scratch (device globals: allocation-free per harness rules)
// ---------------------------------------------------------------------------
__device__ float g_XN [(size_t)MM * DH];   // _x  = LN(x)
__device__ float g_U  [(size_t)MM * DH];   // u -> cx (scan in place)
__device__ float g_CN [(size_t)MM * DH];   // LN(cx)
__device__ float g_OUT[(size_t)MM * DH];   // out
__device__ float g_G  [(size_t)MM * DH];   // gate pre-activation
__device__ float g_DECAY[DH];
__device__ float g_DBETA[DH];

// ---------------------------------------------------------------------------
// decay vector: decay_i = 0.5 ** (1 / linspace(2, 8, D))  == exp2(-1/k)
// ---------------------------------------------------------------------------
__global__ void init_decay_kernel() {
    int h = blockIdx.x * blockDim.x + threadIdx.x;
    if (h < DH) {
        float k = 2.0f + 6.0f * (float)h / (float)(DH - 1);
        float d = exp2f(-1.0f / k);
        g_DECAY[h] = d;
        g_DBETA[h] = 1.0f - d;
    }
}

// ---------------------------------------------------------------------------
// Row LayerNorm: one block (256 thr) per row of 1024. float4 everywhere.
// ---------------------------------------------------------------------------
__global__ void ln_kernel(const float* __restrict__ X,
                          const float* __restrict__ w,
                          const float* __restrict__ b,
                          float* __restrict__ Y) {
    int row = blockIdx.x;
    int t   = threadIdx.x;                     // 0..255
    const float4* xr = (const float4*)(X + (size_t)row * DH);
    float4*       yr = (float4*)(Y + (size_t)row * DH);

    float4 v = xr[t];
    float s = v.x + v.y + v.z + v.w;
    float q = v.x * v.x + v.y * v.y + v.z * v.z + v.w * v.w;
    #pragma unroll
    for (int o = 16; o; o >>= 1) {
        s += __shfl_xor_sync(0xffffffffu, s, o);
        q += __shfl_xor_sync(0xffffffffu, q, o);
    }
    __shared__ float red_s[8], red_q[8];
    __shared__ float s_mu, s_rstd;
    int wid = t >> 5, lane = t & 31;
    if (lane == 0) { red_s[wid] = s; red_q[wid] = q; }
    __syncthreads();
    if (wid == 0) {
        float s2 = (lane < 8) ? red_s[lane] : 0.f;
        float q2 = (lane < 8) ? red_q[lane] : 0.f;
        #pragma unroll
        for (int o = 4; o; o >>= 1) {
            s2 += __shfl_xor_sync(0xffffffffu, s2, o);
            q2 += __shfl_xor_sync(0xffffffffu, q2, o);
        }
        if (lane == 0) {
            float mu  = s2 * (1.0f / DH);
            float var = q2 * (1.0f / DH) - mu * mu;
            s_mu = mu;
            s_rstd = rsqrtf(var + 1e-6f);
        }
    }
    __syncthreads();
    float mu = s_mu, r = s_rstd;
    float4 wv = ((const float4*)w)[t];
    float4 bv = ((const float4*)b)[t];
    float4 o;
    o.x = (v.x - mu) * r * wv.x + bv.x;
    o.y = (v.y - mu) * r * wv.y + bv.y;
    o.z = (v.z - mu) * r * wv.z + bv.z;
    o.w = (v.w - mu) * r * wv.w + bv.w;
    yr[t] = o;
}

// ---------------------------------------------------------------------------
// SGEMM: C[M,N] = concat_A @ Bmat, 128x128 block, BK=16, 8x8 microtile,
// double buffered smem. A rows have stride Ksplit; k >= Ksplit reads A2.
// Optional per-column scale and bias in epilogue.
// ---------------------------------------------------------------------------
__global__ __launch_bounds__(256, 2)
void gemm128_kernel(const float* __restrict__ A,
                    const float* __restrict__ A2,
                    const float* __restrict__ Bm,
                    float* __restrict__ C,
                    int N, int K, int Ksplit,
                    const float* __restrict__ colScale,
                    const float* __restrict__ bias) {
    __shared__ float As[2][16][128];
    __shared__ float Bs[2][16][128];

    const int tid = threadIdx.x;
    const int tx = tid & 15;       // N sub
    const int ty = tid >> 4;       // M sub
    const int blockM = blockIdx.y * 128;
    const int blockN = blockIdx.x * 128;

    // Per-thread load coordinates (2 float4 each for A and B tiles)
    // A tile: 128 rows x 16 k   -> idx: row = idx>>2, q = idx&3 (q*4 = k offset)
    // B tile: 16 rows(k) x 128  -> idx: krow = idx>>5, c4 = idx&31
    float4 pa[2], pb[2];

    const int NT = K / 16;

    // prologue: tile 0
    #pragma unroll
    for (int i = 0; i < 2; i++) {
        int idx = tid + i * 256;
        int row = idx >> 2, q = idx & 3;
        int k = q * 4;
        const float* base = (k < Ksplit)
            ? (A  + (size_t)(blockM + row) * Ksplit + k)
            : (A2 + (size_t)(blockM + row) * Ksplit + (k - Ksplit));
        pa[i] = *(const float4*)base;
        int krow = idx >> 5, c4 = idx & 31;
        pb[i] = *(const float4*)(Bm + (size_t)krow * N + blockN + c4 * 4);
    }
    #pragma unroll
    for (int i = 0; i < 2; i++) {
        int idx = tid + i * 256;
        int row = idx >> 2, q = idx & 3;
        As[0][q * 4 + 0][row] = pa[i].x;
        As[0][q * 4 + 1][row] = pa[i].y;
        As[0][q * 4 + 2][row] = pa[i].z;
        As[0][q * 4 + 3][row] = pa[i].w;
        int krow = idx >> 5, c4 = idx & 31;
        *(float4*)&Bs[0][krow][c4 * 4] = pb[i];
    }
    __syncthreads();

    float acc[8][8];
    #pragma unroll
    for (int i = 0; i < 8; i++)
        #pragma unroll
        for (int j = 0; j < 8; j++) acc[i][j] = 0.f;

    int buf = 0;
    for (int t = 0; t < NT; t++) {
        if (t + 1 < NT) {
            int k0 = (t + 1) * 16;
            #pragma unroll
            for (int i = 0; i < 2; i++) {
                int idx = tid + i * 256;
                int row = idx >> 2, q = idx & 3;
                int k = k0 + q * 4;
                const float* base = (k < Ksplit)
                    ? (A  + (size_t)(blockM + row) * Ksplit + k)
                    : (A2 + (size_t)(blockM + row) * Ksplit + (k - Ksplit));
                pa[i] = *(const float4*)base;
                int krow = idx >> 5, c4 = idx & 31;
                pb[i] = *(const float4*)(Bm + (size_t)(k0 + krow) * N + blockN + c4 * 4);
            }
        }
        const float* Ab = &As[buf][0][0];
        const float* Bb = &Bs[buf][0][0];
        #pragma unroll
        for (int kk = 0; kk < 16; kk++) {
            float4 a0 = *(const float4*)(Ab + kk * 128 + ty * 4);
            float4 a1 = *(const float4*)(Ab + kk * 128 + ty * 4 + 64);
            float4 b0 = *(const float4*)(Bb + kk * 128 + tx * 4);
            float4 b1 = *(const float4*)(Bb + kk * 128 + tx * 4 + 64);
            float av[8] = {a0.x, a0.y, a0.z, a0.w, a1.x, a1.y, a1.z, a1.w};
            float bv[8] = {b0.x, b0.y, b0.z, b0.w, b1.x, b1.y, b1.z, b1.w};
            #pragma unroll
            for (int i = 0; i < 8; i++)
                #pragma unroll
                for (int j = 0; j < 8; j++)
                    acc[i][j] = fmaf(av[i], bv[j], acc[i][j]);
        }
        if (t + 1 < NT) {
            int nb = buf ^ 1;
            #pragma unroll
            for (int i = 0; i < 2; i++) {
                int idx = tid + i * 256;
                int row = idx >> 2, q = idx & 3;
                As[nb][q * 4 + 0][row] = pa[i].x;
                As[nb][q * 4 + 1][row] = pa[i].y;
                As[nb][q * 4 + 2][row] = pa[i].z;
                As[nb][q * 4 + 3][row] = pa[i].w;
                int krow = idx >> 5, c4 = idx & 31;
                *(float4*)&Bs[nb][krow][c4 * 4] = pb[i];
            }
            __syncthreads();
            buf = nb;
        }
    }

    // epilogue
    int nIdx0 = blockN + tx * 4;
    int nIdx4 = blockN + tx * 4 + 64;
    float sc[8], bi[8];
    #pragma unroll
    for (int j = 0; j < 8; j++) {
        int n = (j < 4) ? (nIdx0 + j) : (nIdx4 + j - 4);
        sc[j] = colScale ? colScale[n] : 1.0f;
        bi[j] = bias ? bias[n] : 0.0f;
    }
    #pragma unroll
    for (int i = 0; i < 8; i++) {
        int m = blockM + ((i < 4) ? (ty * 4 + i) : (64 + ty * 4 + (i - 4)));
        float4 o0, o1;
        o0.x = acc[i][0] * sc[0] + bi[0];
        o0.y = acc[i][1] * sc[1] + bi[1];
        o0.z = acc[i][2] * sc[2] + bi[2];
        o0.w = acc[i][3] * sc[3] + bi[3];
        o1.x = acc[i][4] * sc[4] + bi[4];
        o1.y = acc[i][5] * sc[5] + bi[5];
        o1.z = acc[i][6] * sc[6] + bi[6];
        o1.w = acc[i][7] * sc[7] + bi[7];
        *(float4*)&C[(size_t)m * N + nIdx0] = o0;
        *(float4*)&C[(size_t)m * N + nIdx4] = o1;
    }
}

// ---------------------------------------------------------------------------
// Sequential decay scan, in place on U. One thread per (b, h) chain.
// cx[t] = decay[h] * cx[t-1] + u[t]
// ---------------------------------------------------------------------------
__global__ void scan_kernel(float* __restrict__ U) {
    int idx = blockIdx.x * blockDim.x + threadIdx.x;   // 0 .. B*H-1
    int b = idx >> 10;
    int h = idx & 1023;
    float d = g_DECAY[h];
    float* p = U + (size_t)b * SS * DH + h;
    float c = 0.f;
    for (int t0 = 0; t0 < SS; t0 += 8) {
        float v[8];
        #pragma unroll
        for (int j = 0; j < 8; j++) v[j] = p[(size_t)(t0 + j) * DH];
        #pragma unroll
        for (int j = 0; j < 8; j++) {
            c = fmaf(d, c, v[j]);
            p[(size_t)(t0 + j) * DH] = c;
        }
    }
}

// ---------------------------------------------------------------------------
// Final: gate = sigmoid(LN(g)); y = (1-gate)*res + gate*out
// ---------------------------------------------------------------------------
__global__ void gate_kernel(const float* __restrict__ G,
                            const float* __restrict__ RES,
                            const float* __restrict__ OUTm,
                            const float* __restrict__ w,
                            const float* __restrict__ b,
                            float* __restrict__ Y) {
    int row = blockIdx.x;
    int t   = threadIdx.x;
    const float4* gr = (const float4*)(G + (size_t)row * DH);
    float4 v = gr[t];
    float s = v.x + v.y + v.z + v.w;
    float q = v.x * v.x + v.y * v.y + v.z * v.z + v.w * v.w;
    #pragma unroll
    for (int o = 16; o; o >>= 1) {
        s += __shfl_xor_sync(0xffffffffu, s, o);
        q += __shfl_xor_sync(0xffffffffu, q, o);
    }
    __shared__ float red_s[8], red_q[8];
    __shared__ float s_mu, s_rstd;
    int wid = t >> 5, lane = t & 31;
    if (lane == 0) { red_s[wid] = s; red_q[wid] = q; }
    __syncthreads();
    if (wid == 0) {
        float s2 = (lane < 8) ? red_s[lane] : 0.f;
        float q2 = (lane < 8) ? red_q[lane] : 0.f;
        #pragma unroll
        for (int o = 4; o; o >>= 1) {
            s2 += __shfl_xor_sync(0xffffffffu, s2, o);
            q2 += __shfl_xor_sync(0xffffffffu, q2, o);
        }
        if (lane == 0) {
            float mu  = s2 * (1.0f / DH);
            float var = q2 * (1.0f / DH) - mu * mu;
            s_mu = mu;
            s_rstd = rsqrtf(var + 1e-6f);
        }
    }
    __syncthreads();
    float mu = s_mu, r = s_rstd;
    float4 wv = ((const float4*)w)[t];
    float4 bv = ((const float4*)b)[t];
    float4 res = ((const float4*)(RES + (size_t)row * DH))[t];
    float4 ov  = ((const float4*)(OUTm + (size_t)row * DH))[t];

    float z0 = (v.x - mu) * r * wv.x + bv.x;
    float z1 = (v.y - mu) * r * wv.y + bv.y;
    float z2 = (v.z - mu) * r * wv.z + bv.z;
    float z3 = (v.w - mu) * r * wv.w + bv.w;
    float g0 = 1.0f / (1.0f + expf(-z0));
    float g1 = 1.0f / (1.0f + expf(-z1));
    float g2 = 1.0f / (1.0f + expf(-z2));
    float g3 = 1.0f / (1.0f + expf(-z3));

    float4 y;
    y.x = res.x + g0 * (ov.x - res.x);
    y.y = res.y + g1 * (ov.y - res.y);
    y.z = res.z + g2 * (ov.z - res.z);
    y.w = res.w + g3 * (ov.w - res.w);
    ((float4*)(Y + (size_t)row * DH))[t] = y;
}

// ---------------------------------------------------------------------------
// Launch
// ---------------------------------------------------------------------------
extern "C" void kernel_launch(void* const* d_in, const int* in_sizes, int n_in,
                              void* d_out, int out_size) {
    const float* x     = (const float*)d_in[0];
    const float* Wt    = (const float*)d_in[1];
    const float* Wo    = (const float*)d_in[2];
    const float* Wg    = (const float*)d_in[3];
    const float* bg    = (const float*)d_in[4];
    const float* ln1_w = (const float*)d_in[5];
    const float* ln1_b = (const float*)d_in[6];
    const float* lnc_w = (const float*)d_in[7];
    const float* lnc_b = (const float*)d_in[8];
    const float* lng_w = (const float*)d_in[9];
    const float* lng_b = (const float*)d_in[10];
    float* out = (float*)d_out;

    float *XN, *U, *CN, *OT, *G, *DBETA;
    cudaGetSymbolAddress((void**)&XN,    g_XN);
    cudaGetSymbolAddress((void**)&U,     g_U);
    cudaGetSymbolAddress((void**)&CN,    g_CN);
    cudaGetSymbolAddress((void**)&OT,    g_OUT);
    cudaGetSymbolAddress((void**)&G,     g_G);
    cudaGetSymbolAddress((void**)&DBETA, g_DBETA);

    init_decay_kernel<<<4, 256>>>();

    // _x = LN(x)
    ln_kernel<<<MM, 256>>>(x, ln1_w, ln1_b, XN);

    dim3 ggrid(DH / 128, MM / 128);  // (8, 128)

    // u = (_x @ Wt) * decay_beta
    gemm128_kernel<<<ggrid, 256>>>(XN, nullptr, Wt, U, DH, DH, DH, DBETA, nullptr);

    // cx = decay scan (in place on U)
    scan_kernel<<<(BB * DH) / 128, 128>>>(U);

    // CN = LN(cx)
    ln_kernel<<<MM, 256>>>(U, lnc_w, lnc_b, CN);

    // out = CN @ Wo
    gemm128_kernel<<<ggrid, 256>>>(CN, nullptr, Wo, OT, DH, DH, DH, nullptr, nullptr);

    // g = concat(_x, out) @ Wg + bg
    gemm128_kernel<<<ggrid, 256>>>(XN, OT, Wg, G, DH, 2 * DH, DH, nullptr, bg);

    // y = (1-sigmoid(LN(g))) * _x + sigmoid(LN(g)) * out
    gate_kernel<<<MM, 256>>>(G, XN, OT, lng_w, lng_b, out);
}

// round 6
// speedup vs baseline: 2.0811x; 2.0811x over previous
#include <cuda_runtime.h>
#include <cuda_bf16.h>
#include <cstdint>
#include <math.h>

typedef unsigned int u32;

// Problem shape (fixed by setup_inputs): B=8, S=2048, D=H=1024
#define DH   1024
#define BB   8
#define SS   2048
#define MM   (BB * SS)          // 16384 rows

typedef __nv_bfloat16 bf16;

// ---------------------------------------------------------------------------
// Scratch (device globals: allocation-free per harness rules)
// ---------------------------------------------------------------------------
__device__ float g_XN [(size_t)MM * DH];      // _x  = LN(x), fp32 (residual)
__device__ float g_U  [(size_t)MM * DH];      // u -> cx (scan in place)
__device__ float g_OUT[(size_t)MM * DH];      // out (fp32, for gate)
__device__ float g_G  [(size_t)MM * DH];      // gate pre-activation

__device__ bf16  g_AH [(size_t)MM * 2 * DH];  // [x_hi | out_hi]  (M x 2048)
__device__ bf16  g_AL [(size_t)MM * 2 * DH];  // [x_lo | out_lo]
__device__ bf16  g_CNh[(size_t)MM * DH];      // LN(cx) hi
__device__ bf16  g_CNl[(size_t)MM * DH];      // LN(cx) lo

__device__ bf16  g_WtH[(size_t)DH * DH];
__device__ bf16  g_WtL[(size_t)DH * DH];
__device__ bf16  g_WoH[(size_t)DH * DH];
__device__ bf16  g_WoL[(size_t)DH * DH];
__device__ bf16  g_WgH[(size_t)2 * DH * DH];
__device__ bf16  g_WgL[(size_t)2 * DH * DH];

__device__ float g_DECAY[DH];
__device__ float g_DBETA[DH];

// ---------------------------------------------------------------------------
// decay vector: decay_i = 0.5 ** (1 / linspace(2, 8, D))  == exp2(-1/k)
// ---------------------------------------------------------------------------
__global__ void init_decay_kernel() {
    int h = blockIdx.x * blockDim.x + threadIdx.x;
    if (h < DH) {
        float k = 2.0f + 6.0f * (float)h / (float)(DH - 1);
        float d = exp2f(-1.0f / k);
        g_DECAY[h] = d;
        g_DBETA[h] = 1.0f - d;
    }
}

// ---------------------------------------------------------------------------
// fp32 -> (hi, lo) bf16 split, elementwise (for weights)
// ---------------------------------------------------------------------------
__global__ void split_kernel(const float* __restrict__ X,
                             bf16* __restrict__ H, bf16* __restrict__ L,
                             int n4) {
    int i = blockIdx.x * blockDim.x + threadIdx.x;
    if (i < n4) {
        float4 v = ((const float4*)X)[i];
        bf16 h0 = __float2bfloat16_rn(v.x);
        bf16 h1 = __float2bfloat16_rn(v.y);
        bf16 h2 = __float2bfloat16_rn(v.z);
        bf16 h3 = __float2bfloat16_rn(v.w);
        __nv_bfloat162 hh0; hh0.x = h0; hh0.y = h1;
        __nv_bfloat162 hh1; hh1.x = h2; hh1.y = h3;
        __nv_bfloat162 ll0, ll1;
        ll0.x = __float2bfloat16_rn(v.x - __bfloat162float(h0));
        ll0.y = __float2bfloat16_rn(v.y - __bfloat162float(h1));
        ll1.x = __float2bfloat16_rn(v.z - __bfloat162float(h2));
        ll1.y = __float2bfloat16_rn(v.w - __bfloat162float(h3));
        ((__nv_bfloat162*)H)[i * 2 + 0] = hh0;
        ((__nv_bfloat162*)H)[i * 2 + 1] = hh1;
        ((__nv_bfloat162*)L)[i * 2 + 0] = ll0;
        ((__nv_bfloat162*)L)[i * 2 + 1] = ll1;
    }
}

// ---------------------------------------------------------------------------
// Row LayerNorm: one block (256 thr) per row of 1024.
// Optional fp32 output Yf (stride DH) and hi/lo bf16 outputs (stride ldo).
// ---------------------------------------------------------------------------
__global__ void ln_kernel(const float* __restrict__ X,
                          const float* __restrict__ w,
                          const float* __restrict__ b,
                          float* __restrict__ Yf,
                          bf16* __restrict__ Yh,
                          bf16* __restrict__ Yl,
                          int ldo) {
    int row = blockIdx.x;
    int t   = threadIdx.x;                     // 0..255
    const float4* xr = (const float4*)(X + (size_t)row * DH);

    float4 v = xr[t];
    float s = v.x + v.y + v.z + v.w;
    float q = v.x * v.x + v.y * v.y + v.z * v.z + v.w * v.w;
    #pragma unroll
    for (int o = 16; o; o >>= 1) {
        s += __shfl_xor_sync(0xffffffffu, s, o);
        q += __shfl_xor_sync(0xffffffffu, q, o);
    }
    __shared__ float red_s[8], red_q[8];
    __shared__ float s_mu, s_rstd;
    int wid = t >> 5, lane = t & 31;
    if (lane == 0) { red_s[wid] = s; red_q[wid] = q; }
    __syncthreads();
    if (wid == 0) {
        float s2 = (lane < 8) ? red_s[lane] : 0.f;
        float q2 = (lane < 8) ? red_q[lane] : 0.f;
        #pragma unroll
        for (int o = 4; o; o >>= 1) {
            s2 += __shfl_xor_sync(0xffffffffu, s2, o);
            q2 += __shfl_xor_sync(0xffffffffu, q2, o);
        }
        if (lane == 0) {
            float mu  = s2 * (1.0f / DH);
            float var = q2 * (1.0f / DH) - mu * mu;
            s_mu = mu;
            s_rstd = rsqrtf(var + 1e-6f);
        }
    }
    __syncthreads();
    float mu = s_mu, r = s_rstd;
    float4 wv = ((const float4*)w)[t];
    float4 bv = ((const float4*)b)[t];
    float o0 = (v.x - mu) * r * wv.x + bv.x;
    float o1 = (v.y - mu) * r * wv.y + bv.y;
    float o2 = (v.z - mu) * r * wv.z + bv.z;
    float o3 = (v.w - mu) * r * wv.w + bv.w;

    if (Yf) {
        float4 o; o.x = o0; o.y = o1; o.z = o2; o.w = o3;
        ((float4*)(Yf + (size_t)row * DH))[t] = o;
    }
    // hi/lo split
    bf16 h0 = __float2bfloat16_rn(o0);
    bf16 h1 = __float2bfloat16_rn(o1);
    bf16 h2 = __float2bfloat16_rn(o2);
    bf16 h3 = __float2bfloat16_rn(o3);
    __nv_bfloat162 hh0; hh0.x = h0; hh0.y = h1;
    __nv_bfloat162 hh1; hh1.x = h2; hh1.y = h3;
    __nv_bfloat162 ll0, ll1;
    ll0.x = __float2bfloat16_rn(o0 - __bfloat162float(h0));
    ll0.y = __float2bfloat16_rn(o1 - __bfloat162float(h1));
    ll1.x = __float2bfloat16_rn(o2 - __bfloat162float(h2));
    ll1.y = __float2bfloat16_rn(o3 - __bfloat162float(h3));
    bf16* ph = Yh + (size_t)row * ldo + t * 4;
    bf16* pl = Yl + (size_t)row * ldo + t * 4;
    *(__nv_bfloat162*)(ph)     = hh0;
    *(__nv_bfloat162*)(ph + 2) = hh1;
    *(__nv_bfloat162*)(pl)     = ll0;
    *(__nv_bfloat162*)(pl + 2) = ll1;
}

// ---------------------------------------------------------------------------
// Tensor-core GEMM with 3-term bf16 split: C = Ah*Bh + Ah*Bl + Al*Bh
// Block tile 128x128, BK=32, 8 warps (4x2), warp tile 32x64, m16n8k16 mma.
// A: [M, lda] bf16 row-major (k contiguous). B: [K, 1024] bf16 row-major.
// Epilogue: Cf (fp32, optional colScale/bias), optional hi/lo bf16 outputs.
// ---------------------------------------------------------------------------
#define LDA_S 40
#define LDB_S 136

__device__ __forceinline__ void ldsm_x4(u32 r[4], u32 addr) {
    asm volatile("ldmatrix.sync.aligned.m8n8.x4.shared.b16 {%0,%1,%2,%3}, [%4];"
                 : "=r"(r[0]), "=r"(r[1]), "=r"(r[2]), "=r"(r[3]) : "r"(addr));
}
__device__ __forceinline__ void ldsm_x4t(u32 r[4], u32 addr) {
    asm volatile("ldmatrix.sync.aligned.m8n8.x4.trans.shared.b16 {%0,%1,%2,%3}, [%4];"
                 : "=r"(r[0]), "=r"(r[1]), "=r"(r[2]), "=r"(r[3]) : "r"(addr));
}
__device__ __forceinline__ void mma16816(float c[4], const u32 a[4], const u32* b) {
    asm volatile("mma.sync.aligned.m16n8k16.row.col.f32.bf16.bf16.f32 "
                 "{%0,%1,%2,%3}, {%4,%5,%6,%7}, {%8,%9}, {%0,%1,%2,%3};"
                 : "+f"(c[0]), "+f"(c[1]), "+f"(c[2]), "+f"(c[3])
                 : "r"(a[0]), "r"(a[1]), "r"(a[2]), "r"(a[3]), "r"(b[0]), "r"(b[1]));
}

__global__ __launch_bounds__(256)
void gemm_split_kernel(const bf16* __restrict__ Ah, const bf16* __restrict__ Al, int lda,
                       const bf16* __restrict__ Bh, const bf16* __restrict__ Bl, int K,
                       float* __restrict__ Cf,
                       const float* __restrict__ colScale,
                       const float* __restrict__ bias,
                       bf16* __restrict__ Ch, bf16* __restrict__ Cl,
                       int ldc2, int ccol) {
    __shared__ bf16 As[2][128 * LDA_S];
    __shared__ bf16 Bs[2][32 * LDB_S];

    const int tid = threadIdx.x;
    const int lane = tid & 31;
    const int wid = tid >> 5;
    const int wm = wid & 3;        // 0..3  -> M offset wm*32
    const int wn = wid >> 2;       // 0..1  -> N offset wn*64
    const int blockM = blockIdx.y * 128;
    const int blockN = blockIdx.x * 128;

    const int NT = K / 32;
    const int TT = 3 * NT;

    // global load coords
    const int arow = tid >> 2, ac = (tid & 3) * 8;              // A: +i*64 rows
    const int bkrow = tid >> 4, bc = (tid & 15) * 8;            // B: +i*16 rows

    u32 asBase = (u32)__cvta_generic_to_shared(&As[0][0]);
    u32 bsBase = (u32)__cvta_generic_to_shared(&Bs[0][0]);
    const u32 asStride = 128 * LDA_S * 2;
    const u32 bsStride = 32 * LDB_S * 2;

    // ldmatrix lane addressing (element offsets within a buffer)
    const int a_row_l = wm * 32 + (lane & 15);
    const int a_k_l   = (lane >> 4) * 8;
    const int b_g = lane >> 3, b_r = lane & 7;
    const int b_krow_l = (b_g & 1) * 8 + b_r;
    const int b_n_l    = wn * 64 + (b_g >> 1) * 8;

    uint4 pa[2], pb[2];

    // ---- prologue: fetch tile 0 (pass 0: Ah, Bh; k0 = 0)
    #pragma unroll
    for (int i = 0; i < 2; i++) {
        pa[i] = *(const uint4*)(Ah + (size_t)(blockM + arow + i * 64) * lda + ac);
        pb[i] = *(const uint4*)(Bh + (size_t)(bkrow + i * 16) * 1024 + blockN + bc);
    }
    #pragma unroll
    for (int i = 0; i < 2; i++) {
        *(uint4*)&As[0][(arow + i * 64) * LDA_S + ac] = pa[i];
        *(uint4*)&Bs[0][(bkrow + i * 16) * LDB_S + bc] = pb[i];
    }
    __syncthreads();

    float acc[2][8][4];
    #pragma unroll
    for (int mi = 0; mi < 2; mi++)
        #pragma unroll
        for (int ni = 0; ni < 8; ni++)
            #pragma unroll
            for (int j = 0; j < 4; j++) acc[mi][ni][j] = 0.f;

    int buf = 0;
    for (int t = 0; t < TT; t++) {
        if (t + 1 < TT) {
            int tn = t + 1;
            int p  = (tn >= 2 * NT) ? 2 : ((tn >= NT) ? 1 : 0);
            int k0 = (tn - p * NT) * 32;
            const bf16* Aop = (p == 2) ? Al : Ah;
            const bf16* Bop = (p == 1) ? Bl : Bh;
            #pragma unroll
            for (int i = 0; i < 2; i++) {
                pa[i] = *(const uint4*)(Aop + (size_t)(blockM + arow + i * 64) * lda + k0 + ac);
                pb[i] = *(const uint4*)(Bop + (size_t)(k0 + bkrow + i * 16) * 1024 + blockN + bc);
            }
        }
        u32 asB = asBase + buf * asStride;
        u32 bsB = bsBase + buf * bsStride;
        #pragma unroll
        for (int kk = 0; kk < 2; kk++) {
            u32 afrag[2][4];
            #pragma unroll
            for (int mi = 0; mi < 2; mi++) {
                u32 addr = asB + ((a_row_l + mi * 16) * LDA_S + kk * 16 + a_k_l) * 2;
                ldsm_x4(afrag[mi], addr);
            }
            u32 bfrag[8][2];
            #pragma unroll
            for (int np = 0; np < 4; np++) {
                u32 r[4];
                u32 addr = bsB + ((kk * 16 + b_krow_l) * LDB_S + b_n_l + np * 16) * 2;
                ldsm_x4t(r, addr);
                bfrag[np * 2 + 0][0] = r[0]; bfrag[np * 2 + 0][1] = r[1];
                bfrag[np * 2 + 1][0] = r[2]; bfrag[np * 2 + 1][1] = r[3];
            }
            #pragma unroll
            for (int mi = 0; mi < 2; mi++)
                #pragma unroll
                for (int ni = 0; ni < 8; ni++)
                    mma16816(acc[mi][ni], afrag[mi], bfrag[ni]);
        }
        if (t + 1 < TT) {
            int nb = buf ^ 1;
            #pragma unroll
            for (int i = 0; i < 2; i++) {
                *(uint4*)&As[nb][(arow + i * 64) * LDA_S + ac] = pa[i];
                *(uint4*)&Bs[nb][(bkrow + i * 16) * LDB_S + bc] = pb[i];
            }
            __syncthreads();
            buf = nb;
        }
    }

    // ---- epilogue
    const int gr = lane >> 2;          // 0..7
    const int qc = (lane & 3) * 2;     // 0,2,4,6
    #pragma unroll
    for (int mi = 0; mi < 2; mi++) {
        #pragma unroll
        for (int ni = 0; ni < 8; ni++) {
            int col = blockN + wn * 64 + ni * 8 + qc;
            float sc0 = colScale ? colScale[col]     : 1.0f;
            float sc1 = colScale ? colScale[col + 1] : 1.0f;
            float bi0 = bias ? bias[col]     : 0.0f;
            float bi1 = bias ? bias[col + 1] : 0.0f;
            #pragma unroll
            for (int half = 0; half < 2; half++) {
                int row = blockM + wm * 32 + mi * 16 + gr + half * 8;
                float v0 = acc[mi][ni][half * 2 + 0] * sc0 + bi0;
                float v1 = acc[mi][ni][half * 2 + 1] * sc1 + bi1;
                float2 o; o.x = v0; o.y = v1;
                *(float2*)&Cf[(size_t)row * 1024 + col] = o;
                if (Ch) {
                    __nv_bfloat162 hh, ll;
                    hh.x = __float2bfloat16_rn(v0);
                    hh.y = __float2bfloat16_rn(v1);
                    ll.x = __float2bfloat16_rn(v0 - __bfloat162float(hh.x));
                    ll.y = __float2bfloat16_rn(v1 - __bfloat162float(hh.y));
                    *(__nv_bfloat162*)&Ch[(size_t)row * ldc2 + ccol + col] = hh;
                    *(__nv_bfloat162*)&Cl[(size_t)row * ldc2 + ccol + col] = ll;
                }
            }
        }
    }
}

// ---------------------------------------------------------------------------
// Sequential decay scan, in place on U. One thread per (b, h) chain.
// ---------------------------------------------------------------------------
__global__ void scan_kernel(float* __restrict__ U) {
    int idx = blockIdx.x * blockDim.x + threadIdx.x;   // 0 .. B*H-1
    int b = idx >> 10;
    int h = idx & 1023;
    float d = g_DECAY[h];
    float* p = U + (size_t)b * SS * DH + h;
    float c = 0.f;
    for (int t0 = 0; t0 < SS; t0 += 8) {
        float v[8];
        #pragma unroll
        for (int j = 0; j < 8; j++) v[j] = p[(size_t)(t0 + j) * DH];
        #pragma unroll
        for (int j = 0; j < 8; j++) {
            c = fmaf(d, c, v[j]);
            p[(size_t)(t0 + j) * DH] = c;
        }
    }
}

// ---------------------------------------------------------------------------
// Final: gate = sigmoid(LN(g)); y = (1-gate)*res + gate*out
// ---------------------------------------------------------------------------
__global__ void gate_kernel(const float* __restrict__ G,
                            const float* __restrict__ RES,
                            const float* __restrict__ OUTm,
                            const float* __restrict__ w,
                            const float* __restrict__ b,
                            float* __restrict__ Y) {
    int row = blockIdx.x;
    int t   = threadIdx.x;
    const float4* gr = (const float4*)(G + (size_t)row * DH);
    float4 v = gr[t];
    float s = v.x + v.y + v.z + v.w;
    float q = v.x * v.x + v.y * v.y + v.z * v.z + v.w * v.w;
    #pragma unroll
    for (int o = 16; o; o >>= 1) {
        s += __shfl_xor_sync(0xffffffffu, s, o);
        q += __shfl_xor_sync(0xffffffffu, q, o);
    }
    __shared__ float red_s[8], red_q[8];
    __shared__ float s_mu, s_rstd;
    int wid = t >> 5, lane = t & 31;
    if (lane == 0) { red_s[wid] = s; red_q[wid] = q; }
    __syncthreads();
    if (wid == 0) {
        float s2 = (lane < 8) ? red_s[lane] : 0.f;
        float q2 = (lane < 8) ? red_q[lane] : 0.f;
        #pragma unroll
        for (int o = 4; o; o >>= 1) {
            s2 += __shfl_xor_sync(0xffffffffu, s2, o);
            q2 += __shfl_xor_sync(0xffffffffu, q2, o);
        }
        if (lane == 0) {
            float mu  = s2 * (1.0f / DH);
            float var = q2 * (1.0f / DH) - mu * mu;
            s_mu = mu;
            s_rstd = rsqrtf(var + 1e-6f);
        }
    }
    __syncthreads();
    float mu = s_mu, r = s_rstd;
    float4 wv = ((const float4*)w)[t];
    float4 bv = ((const float4*)b)[t];
    float4 res = ((const float4*)(RES + (size_t)row * DH))[t];
    float4 ov  = ((const float4*)(OUTm + (size_t)row * DH))[t];

    float z0 = (v.x - mu) * r * wv.x + bv.x;
    float z1 = (v.y - mu) * r * wv.y + bv.y;
    float z2 = (v.z - mu) * r * wv.z + bv.z;
    float z3 = (v.w - mu) * r * wv.w + bv.w;
    float g0 = 1.0f / (1.0f + expf(-z0));
    float g1 = 1.0f / (1.0f + expf(-z1));
    float g2 = 1.0f / (1.0f + expf(-z2));
    float g3 = 1.0f / (1.0f + expf(-z3));

    float4 y;
    y.x = res.x + g0 * (ov.x - res.x);
    y.y = res.y + g1 * (ov.y - res.y);
    y.z = res.z + g2 * (ov.z - res.z);
    y.w = res.w + g3 * (ov.w - res.w);
    ((float4*)(Y + (size_t)row * DH))[t] = y;
}

// ---------------------------------------------------------------------------
// Launch
// ---------------------------------------------------------------------------
extern "C" void kernel_launch(void* const* d_in, const int* in_sizes, int n_in,
                              void* d_out, int out_size) {
    const float* x     = (const float*)d_in[0];
    const float* Wt    = (const float*)d_in[1];
    const float* Wo    = (const float*)d_in[2];
    const float* Wg    = (const float*)d_in[3];
    const float* bg    = (const float*)d_in[4];
    const float* ln1_w = (const float*)d_in[5];
    const float* ln1_b = (const float*)d_in[6];
    const float* lnc_w = (const float*)d_in[7];
    const float* lnc_b = (const float*)d_in[8];
    const float* lng_w = (const float*)d_in[9];
    const float* lng_b = (const float*)d_in[10];
    float* out = (float*)d_out;

    float *XN, *U, *OT, *G, *DBETA;
    bf16 *AH, *AL, *CNh, *CNl, *WtH, *WtL, *WoH, *WoL, *WgH, *WgL;
    cudaGetSymbolAddress((void**)&XN,  g_XN);
    cudaGetSymbolAddress((void**)&U,   g_U);
    cudaGetSymbolAddress((void**)&OT,  g_OUT);
    cudaGetSymbolAddress((void**)&G,   g_G);
    cudaGetSymbolAddress((void**)&DBETA, g_DBETA);
    cudaGetSymbolAddress((void**)&AH,  g_AH);
    cudaGetSymbolAddress((void**)&AL,  g_AL);
    cudaGetSymbolAddress((void**)&CNh, g_CNh);
    cudaGetSymbolAddress((void**)&CNl, g_CNl);
    cudaGetSymbolAddress((void**)&WtH, g_WtH);
    cudaGetSymbolAddress((void**)&WtL, g_WtL);
    cudaGetSymbolAddress((void**)&WoH, g_WoH);
    cudaGetSymbolAddress((void**)&WoL, g_WoL);
    cudaGetSymbolAddress((void**)&WgH, g_WgH);
    cudaGetSymbolAddress((void**)&WgL, g_WgL);

    init_decay_kernel<<<4, 256>>>();

    // weight splits
    split_kernel<<<(DH * DH / 4 + 255) / 256, 256>>>(Wt, WtH, WtL, DH * DH / 4);
    split_kernel<<<(DH * DH / 4 + 255) / 256, 256>>>(Wo, WoH, WoL, DH * DH / 4);
    split_kernel<<<(2 * DH * DH / 4 + 255) / 256, 256>>>(Wg, WgH, WgL, 2 * DH * DH / 4);

    // _x = LN(x): fp32 residual + hi/lo into concat buffer cols [0,1024)
    ln_kernel<<<MM, 256>>>(x, ln1_w, ln1_b, XN, AH, AL, 2 * DH);

    dim3 ggrid(DH / 128, MM / 128);  // (8, 128)

    // u = (_x @ Wt) * decay_beta
    gemm_split_kernel<<<ggrid, 256>>>(AH, AL, 2 * DH, WtH, WtL, DH,
                                      U, DBETA, nullptr,
                                      nullptr, nullptr, 0, 0);

    // cx = decay scan (in place on U)
    scan_kernel<<<(BB * DH) / 128, 128>>>(U);

    // LN(cx) -> hi/lo only
    ln_kernel<<<MM, 256>>>(U, lnc_w, lnc_b, nullptr, CNh, CNl, DH);

    // out = LN(cx) @ Wo : fp32 OT + hi/lo into concat buffer cols [1024,2048)
    gemm_split_kernel<<<ggrid, 256>>>(CNh, CNl, DH, WoH, WoL, DH,
                                      OT, nullptr, nullptr,
                                      AH, AL, 2 * DH, DH);

    // g = concat(_x, out) @ Wg + bg   (K = 2048, concat buffer is contiguous)
    gemm_split_kernel<<<ggrid, 256>>>(AH, AL, 2 * DH, WgH, WgL, 2 * DH,
                                      G, nullptr, bg,
                                      nullptr, nullptr, 0, 0);

    // y = (1-sigmoid(LN(g))) * _x + sigmoid(LN(g)) * out
    gate_kernel<<<MM, 256>>>(G, XN, OT, lng_w, lng_b, out);
}

// round 7
// speedup vs baseline: 2.0848x; 1.0018x over previous
#include <cuda_runtime.h>
#include <cuda_bf16.h>
#include <cstdint>
#include <math.h>

typedef unsigned int u32;

// Problem shape (fixed by setup_inputs): B=8, S=2048, D=H=1024
#define DH   1024
#define BB   8
#define SS   2048
#define MM   (BB * SS)          // 16384 rows

typedef __nv_bfloat16 bf16;

// ---------------------------------------------------------------------------
// Scratch (device globals: allocation-free per harness rules)
// ---------------------------------------------------------------------------
__device__ float g_XN [(size_t)MM * DH];      // _x  = LN(x), fp32 (residual)
__device__ float g_U  [(size_t)MM * DH];      // u -> cx (scan in place)
__device__ float g_OUT[(size_t)MM * DH];      // out (fp32, for gate)
__device__ float g_G  [(size_t)MM * DH];      // gate pre-activation

__device__ bf16  g_AH [(size_t)MM * 2 * DH];  // [x_hi | out_hi]  (M x 2048)
__device__ bf16  g_AL [(size_t)MM * 2 * DH];  // [x_lo | out_lo]
__device__ bf16  g_CNh[(size_t)MM * DH];      // LN(cx) hi
__device__ bf16  g_CNl[(size_t)MM * DH];      // LN(cx) lo

__device__ bf16  g_WtH[(size_t)DH * DH];
__device__ bf16  g_WtL[(size_t)DH * DH];
__device__ bf16  g_WoH[(size_t)DH * DH];
__device__ bf16  g_WoL[(size_t)DH * DH];
__device__ bf16  g_WgH[(size_t)2 * DH * DH];
__device__ bf16  g_WgL[(size_t)2 * DH * DH];

__device__ float g_DECAY[DH];
__device__ float g_DBETA[DH];

// ---------------------------------------------------------------------------
// decay vector: decay_i = 0.5 ** (1 / linspace(2, 8, D))  == exp2(-1/k)
// ---------------------------------------------------------------------------
__global__ void init_decay_kernel() {
    int h = blockIdx.x * blockDim.x + threadIdx.x;
    if (h < DH) {
        float k = 2.0f + 6.0f * (float)h / (float)(DH - 1);
        float d = exp2f(-1.0f / k);
        g_DECAY[h] = d;
        g_DBETA[h] = 1.0f - d;
    }
}

// ---------------------------------------------------------------------------
// fp32 -> (hi, lo) bf16 split, elementwise (for weights)
// ---------------------------------------------------------------------------
__global__ void split_kernel(const float* __restrict__ X,
                             bf16* __restrict__ H, bf16* __restrict__ L,
                             int n4) {
    int i = blockIdx.x * blockDim.x + threadIdx.x;
    if (i < n4) {
        float4 v = ((const float4*)X)[i];
        bf16 h0 = __float2bfloat16_rn(v.x);
        bf16 h1 = __float2bfloat16_rn(v.y);
        bf16 h2 = __float2bfloat16_rn(v.z);
        bf16 h3 = __float2bfloat16_rn(v.w);
        __nv_bfloat162 hh0; hh0.x = h0; hh0.y = h1;
        __nv_bfloat162 hh1; hh1.x = h2; hh1.y = h3;
        __nv_bfloat162 ll0, ll1;
        ll0.x = __float2bfloat16_rn(v.x - __bfloat162float(h0));
        ll0.y = __float2bfloat16_rn(v.y - __bfloat162float(h1));
        ll1.x = __float2bfloat16_rn(v.z - __bfloat162float(h2));
        ll1.y = __float2bfloat16_rn(v.w - __bfloat162float(h3));
        ((__nv_bfloat162*)H)[i * 2 + 0] = hh0;
        ((__nv_bfloat162*)H)[i * 2 + 1] = hh1;
        ((__nv_bfloat162*)L)[i * 2 + 0] = ll0;
        ((__nv_bfloat162*)L)[i * 2 + 1] = ll1;
    }
}

// ---------------------------------------------------------------------------
// Row LayerNorm: one block (256 thr) per row of 1024.
// Optional fp32 output Yf (stride DH) and hi/lo bf16 outputs (stride ldo).
// ---------------------------------------------------------------------------
__global__ void ln_kernel(const float* __restrict__ X,
                          const float* __restrict__ w,
                          const float* __restrict__ b,
                          float* __restrict__ Yf,
                          bf16* __restrict__ Yh,
                          bf16* __restrict__ Yl,
                          int ldo) {
    int row = blockIdx.x;
    int t   = threadIdx.x;                     // 0..255
    const float4* xr = (const float4*)(X + (size_t)row * DH);

    float4 v = xr[t];
    float s = v.x + v.y + v.z + v.w;
    float q = v.x * v.x + v.y * v.y + v.z * v.z + v.w * v.w;
    #pragma unroll
    for (int o = 16; o; o >>= 1) {
        s += __shfl_xor_sync(0xffffffffu, s, o);
        q += __shfl_xor_sync(0xffffffffu, q, o);
    }
    __shared__ float red_s[8], red_q[8];
    __shared__ float s_mu, s_rstd;
    int wid = t >> 5, lane = t & 31;
    if (lane == 0) { red_s[wid] = s; red_q[wid] = q; }
    __syncthreads();
    if (wid == 0) {
        float s2 = (lane < 8) ? red_s[lane] : 0.f;
        float q2 = (lane < 8) ? red_q[lane] : 0.f;
        #pragma unroll
        for (int o = 4; o; o >>= 1) {
            s2 += __shfl_xor_sync(0xffffffffu, s2, o);
            q2 += __shfl_xor_sync(0xffffffffu, q2, o);
        }
        if (lane == 0) {
            float mu  = s2 * (1.0f / DH);
            float var = q2 * (1.0f / DH) - mu * mu;
            s_mu = mu;
            s_rstd = rsqrtf(var + 1e-6f);
        }
    }
    __syncthreads();
    float mu = s_mu, r = s_rstd;
    float4 wv = ((const float4*)w)[t];
    float4 bv = ((const float4*)b)[t];
    float o0 = (v.x - mu) * r * wv.x + bv.x;
    float o1 = (v.y - mu) * r * wv.y + bv.y;
    float o2 = (v.z - mu) * r * wv.z + bv.z;
    float o3 = (v.w - mu) * r * wv.w + bv.w;

    if (Yf) {
        float4 o; o.x = o0; o.y = o1; o.z = o2; o.w = o3;
        ((float4*)(Yf + (size_t)row * DH))[t] = o;
    }
    // hi/lo split
    bf16 h0 = __float2bfloat16_rn(o0);
    bf16 h1 = __float2bfloat16_rn(o1);
    bf16 h2 = __float2bfloat16_rn(o2);
    bf16 h3 = __float2bfloat16_rn(o3);
    __nv_bfloat162 hh0; hh0.x = h0; hh0.y = h1;
    __nv_bfloat162 hh1; hh1.x = h2; hh1.y = h3;
    __nv_bfloat162 ll0, ll1;
    ll0.x = __float2bfloat16_rn(o0 - __bfloat162float(h0));
    ll0.y = __float2bfloat16_rn(o1 - __bfloat162float(h1));
    ll1.x = __float2bfloat16_rn(o2 - __bfloat162float(h2));
    ll1.y = __float2bfloat16_rn(o3 - __bfloat162float(h3));
    bf16* ph = Yh + (size_t)row * ldo + t * 4;
    bf16* pl = Yl + (size_t)row * ldo + t * 4;
    *(__nv_bfloat162*)(ph)     = hh0;
    *(__nv_bfloat162*)(ph + 2) = hh1;
    *(__nv_bfloat162*)(pl)     = ll0;
    *(__nv_bfloat162*)(pl + 2) = ll1;
}

// ---------------------------------------------------------------------------
// Tensor-core GEMM with 3-term bf16 split: C = Ah*Bh + Ah*Bl + Al*Bh
// Block tile 128x128, BK=32, 8 warps (4x2), warp tile 32x64, m16n8k16 mma.
// A: [M, lda] bf16 row-major (k contiguous). B: [K, 1024] bf16 row-major.
// Epilogue: Cf (fp32, optional colScale/bias), optional hi/lo bf16 outputs.
// ---------------------------------------------------------------------------
#define LDA_S 40
#define LDB_S 136

__device__ __forceinline__ void ldsm_x4(u32 r[4], u32 addr) {
    asm volatile("ldmatrix.sync.aligned.m8n8.x4.shared.b16 {%0,%1,%2,%3}, [%4];"
                 : "=r"(r[0]), "=r"(r[1]), "=r"(r[2]), "=r"(r[3]) : "r"(addr));
}
__device__ __forceinline__ void ldsm_x4t(u32 r[4], u32 addr) {
    asm volatile("ldmatrix.sync.aligned.m8n8.x4.trans.shared.b16 {%0,%1,%2,%3}, [%4];"
                 : "=r"(r[0]), "=r"(r[1]), "=r"(r[2]), "=r"(r[3]) : "r"(addr));
}
__device__ __forceinline__ void mma16816(float c[4], const u32 a[4], const u32* b) {
    asm volatile("mma.sync.aligned.m16n8k16.row.col.f32.bf16.bf16.f32 "
                 "{%0,%1,%2,%3}, {%4,%5,%6,%7}, {%8,%9}, {%0,%1,%2,%3};"
                 : "+f"(c[0]), "+f"(c[1]), "+f"(c[2]), "+f"(c[3])
                 : "r"(a[0]), "r"(a[1]), "r"(a[2]), "r"(a[3]), "r"(b[0]), "r"(b[1]));
}

__global__ __launch_bounds__(256)
void gemm_split_kernel(const bf16* __restrict__ Ah, const bf16* __restrict__ Al, int lda,
                       const bf16* __restrict__ Bh, const bf16* __restrict__ Bl, int K,
                       float* __restrict__ Cf,
                       const float* __restrict__ colScale,
                       const float* __restrict__ bias,
                       bf16* __restrict__ Ch, bf16* __restrict__ Cl,
                       int ldc2, int ccol) {
    __shared__ bf16 As[2][128 * LDA_S];
    __shared__ bf16 Bs[2][32 * LDB_S];

    const int tid = threadIdx.x;
    const int lane = tid & 31;
    const int wid = tid >> 5;
    const int wm = wid & 3;        // 0..3  -> M offset wm*32
    const int wn = wid >> 2;       // 0..1  -> N offset wn*64
    const int blockM = blockIdx.y * 128;
    const int blockN = blockIdx.x * 128;

    const int NT = K / 32;
    const int TT = 3 * NT;

    // global load coords
    const int arow = tid >> 2, ac = (tid & 3) * 8;              // A: +i*64 rows
    const int bkrow = tid >> 4, bc = (tid & 15) * 8;            // B: +i*16 rows

    u32 asBase = (u32)__cvta_generic_to_shared(&As[0][0]);
    u32 bsBase = (u32)__cvta_generic_to_shared(&Bs[0][0]);
    const u32 asStride = 128 * LDA_S * 2;
    const u32 bsStride = 32 * LDB_S * 2;

    // ldmatrix lane addressing (element offsets within a buffer)
    const int a_row_l = wm * 32 + (lane & 15);
    const int a_k_l   = (lane >> 4) * 8;
    const int b_g = lane >> 3, b_r = lane & 7;
    const int b_krow_l = (b_g & 1) * 8 + b_r;
    const int b_n_l    = wn * 64 + (b_g >> 1) * 8;

    uint4 pa[2], pb[2];

    // ---- prologue: fetch tile 0 (pass 0: Ah, Bh; k0 = 0)
    #pragma unroll
    for (int i = 0; i < 2; i++) {
        pa[i] = *(const uint4*)(Ah + (size_t)(blockM + arow + i * 64) * lda + ac);
        pb[i] = *(const uint4*)(Bh + (size_t)(bkrow + i * 16) * 1024 + blockN + bc);
    }
    #pragma unroll
    for (int i = 0; i < 2; i++) {
        *(uint4*)&As[0][(arow + i * 64) * LDA_S + ac] = pa[i];
        *(uint4*)&Bs[0][(bkrow + i * 16) * LDB_S + bc] = pb[i];
    }
    __syncthreads();

    float acc[2][8][4];
    #pragma unroll
    for (int mi = 0; mi < 2; mi++)
        #pragma unroll
        for (int ni = 0; ni < 8; ni++)
            #pragma unroll
            for (int j = 0; j < 4; j++) acc[mi][ni][j] = 0.f;

    int buf = 0;
    for (int t = 0; t < TT; t++) {
        if (t + 1 < TT) {
            int tn = t + 1;
            int p  = (tn >= 2 * NT) ? 2 : ((tn >= NT) ? 1 : 0);
            int k0 = (tn - p * NT) * 32;
            const bf16* Aop = (p == 2) ? Al : Ah;
            const bf16* Bop = (p == 1) ? Bl : Bh;
            #pragma unroll
            for (int i = 0; i < 2; i++) {
                pa[i] = *(const uint4*)(Aop + (size_t)(blockM + arow + i * 64) * lda + k0 + ac);
                pb[i] = *(const uint4*)(Bop + (size_t)(k0 + bkrow + i * 16) * 1024 + blockN + bc);
            }
        }
        u32 asB = asBase + buf * asStride;
        u32 bsB = bsBase + buf * bsStride;
        #pragma unroll
        for (int kk = 0; kk < 2; kk++) {
            u32 afrag[2][4];
            #pragma unroll
            for (int mi = 0; mi < 2; mi++) {
                u32 addr = asB + ((a_row_l + mi * 16) * LDA_S + kk * 16 + a_k_l) * 2;
                ldsm_x4(afrag[mi], addr);
            }
            u32 bfrag[8][2];
            #pragma unroll
            for (int np = 0; np < 4; np++) {
                u32 r[4];
                u32 addr = bsB + ((kk * 16 + b_krow_l) * LDB_S + b_n_l + np * 16) * 2;
                ldsm_x4t(r, addr);
                bfrag[np * 2 + 0][0] = r[0]; bfrag[np * 2 + 0][1] = r[1];
                bfrag[np * 2 + 1][0] = r[2]; bfrag[np * 2 + 1][1] = r[3];
            }
            #pragma unroll
            for (int mi = 0; mi < 2; mi++)
                #pragma unroll
                for (int ni = 0; ni < 8; ni++)
                    mma16816(acc[mi][ni], afrag[mi], bfrag[ni]);
        }
        if (t + 1 < TT) {
            int nb = buf ^ 1;
            #pragma unroll
            for (int i = 0; i < 2; i++) {
                *(uint4*)&As[nb][(arow + i * 64) * LDA_S + ac] = pa[i];
                *(uint4*)&Bs[nb][(bkrow + i * 16) * LDB_S + bc] = pb[i];
            }
            __syncthreads();
            buf = nb;
        }
    }

    // ---- epilogue
    const int gr = lane >> 2;          // 0..7
    const int qc = (lane & 3) * 2;     // 0,2,4,6
    #pragma unroll
    for (int mi = 0; mi < 2; mi++) {
        #pragma unroll
        for (int ni = 0; ni < 8; ni++) {
            int col = blockN + wn * 64 + ni * 8 + qc;
            float sc0 = colScale ? colScale[col]     : 1.0f;
            float sc1 = colScale ? colScale[col + 1] : 1.0f;
            float bi0 = bias ? bias[col]     : 0.0f;
            float bi1 = bias ? bias[col + 1] : 0.0f;
            #pragma unroll
            for (int half = 0; half < 2; half++) {
                int row = blockM + wm * 32 + mi * 16 + gr + half * 8;
                float v0 = acc[mi][ni][half * 2 + 0] * sc0 + bi0;
                float v1 = acc[mi][ni][half * 2 + 1] * sc1 + bi1;
                float2 o; o.x = v0; o.y = v1;
                *(float2*)&Cf[(size_t)row * 1024 + col] = o;
                if (Ch) {
                    __nv_bfloat162 hh, ll;
                    hh.x = __float2bfloat16_rn(v0);
                    hh.y = __float2bfloat16_rn(v1);
                    ll.x = __float2bfloat16_rn(v0 - __bfloat162float(hh.x));
                    ll.y = __float2bfloat16_rn(v1 - __bfloat162float(hh.y));
                    *(__nv_bfloat162*)&Ch[(size_t)row * ldc2 + ccol + col] = hh;
                    *(__nv_bfloat162*)&Cl[(size_t)row * ldc2 + ccol + col] = ll;
                }
            }
        }
    }
}

// ---------------------------------------------------------------------------
// Sequential decay scan, in place on U. One thread per (b, h) chain.
// ---------------------------------------------------------------------------
__global__ void scan_kernel(float* __restrict__ U) {
    int idx = blockIdx.x * blockDim.x + threadIdx.x;   // 0 .. B*H-1
    int b = idx >> 10;
    int h = idx & 1023;
    float d = g_DECAY[h];
    float* p = U + (size_t)b * SS * DH + h;
    float c = 0.f;
    for (int t0 = 0; t0 < SS; t0 += 8) {
        float v[8];
        #pragma unroll
        for (int j = 0; j < 8; j++) v[j] = p[(size_t)(t0 + j) * DH];
        #pragma unroll
        for (int j = 0; j < 8; j++) {
            c = fmaf(d, c, v[j]);
            p[(size_t)(t0 + j) * DH] = c;
        }
    }
}

// ---------------------------------------------------------------------------
// Final: gate = sigmoid(LN(g)); y = (1-gate)*res + gate*out
// ---------------------------------------------------------------------------
__global__ void gate_kernel(const float* __restrict__ G,
                            const float* __restrict__ RES,
                            const float* __restrict__ OUTm,
                            const float* __restrict__ w,
                            const float* __restrict__ b,
                            float* __restrict__ Y) {
    int row = blockIdx.x;
    int t   = threadIdx.x;
    const float4* gr = (const float4*)(G + (size_t)row * DH);
    float4 v = gr[t];
    float s = v.x + v.y + v.z + v.w;
    float q = v.x * v.x + v.y * v.y + v.z * v.z + v.w * v.w;
    #pragma unroll
    for (int o = 16; o; o >>= 1) {
        s += __shfl_xor_sync(0xffffffffu, s, o);
        q += __shfl_xor_sync(0xffffffffu, q, o);
    }
    __shared__ float red_s[8], red_q[8];
    __shared__ float s_mu, s_rstd;
    int wid = t >> 5, lane = t & 31;
    if (lane == 0) { red_s[wid] = s; red_q[wid] = q; }
    __syncthreads();
    if (wid == 0) {
        float s2 = (lane < 8) ? red_s[lane] : 0.f;
        float q2 = (lane < 8) ? red_q[lane] : 0.f;
        #pragma unroll
        for (int o = 4; o; o >>= 1) {
            s2 += __shfl_xor_sync(0xffffffffu, s2, o);
            q2 += __shfl_xor_sync(0xffffffffu, q2, o);
        }
        if (lane == 0) {
            float mu  = s2 * (1.0f / DH);
            float var = q2 * (1.0f / DH) - mu * mu;
            s_mu = mu;
            s_rstd = rsqrtf(var + 1e-6f);
        }
    }
    __syncthreads();
    float mu = s_mu, r = s_rstd;
    float4 wv = ((const float4*)w)[t];
    float4 bv = ((const float4*)b)[t];
    float4 res = ((const float4*)(RES + (size_t)row * DH))[t];
    float4 ov  = ((const float4*)(OUTm + (size_t)row * DH))[t];

    float z0 = (v.x - mu) * r * wv.x + bv.x;
    float z1 = (v.y - mu) * r * wv.y + bv.y;
    float z2 = (v.z - mu) * r * wv.z + bv.z;
    float z3 = (v.w - mu) * r * wv.w + bv.w;
    float g0 = 1.0f / (1.0f + expf(-z0));
    float g1 = 1.0f / (1.0f + expf(-z1));
    float g2 = 1.0f / (1.0f + expf(-z2));
    float g3 = 1.0f / (1.0f + expf(-z3));

    float4 y;
    y.x = res.x + g0 * (ov.x - res.x);
    y.y = res.y + g1 * (ov.y - res.y);
    y.z = res.z + g2 * (ov.z - res.z);
    y.w = res.w + g3 * (ov.w - res.w);
    ((float4*)(Y + (size_t)row * DH))[t] = y;
}

// ---------------------------------------------------------------------------
// Launch
// ---------------------------------------------------------------------------
extern "C" void kernel_launch(void* const* d_in, const int* in_sizes, int n_in,
                              void* d_out, int out_size) {
    const float* x     = (const float*)d_in[0];
    const float* Wt    = (const float*)d_in[1];
    const float* Wo    = (const float*)d_in[2];
    const float* Wg    = (const float*)d_in[3];
    const float* bg    = (const float*)d_in[4];
    const float* ln1_w = (const float*)d_in[5];
    const float* ln1_b = (const float*)d_in[6];
    const float* lnc_w = (const float*)d_in[7];
    const float* lnc_b = (const float*)d_in[8];
    const float* lng_w = (const float*)d_in[9];
    const float* lng_b = (const float*)d_in[10];
    float* out = (float*)d_out;

    float *XN, *U, *OT, *G, *DBETA;
    bf16 *AH, *AL, *CNh, *CNl, *WtH, *WtL, *WoH, *WoL, *WgH, *WgL;
    cudaGetSymbolAddress((void**)&XN,  g_XN);
    cudaGetSymbolAddress((void**)&U,   g_U);
    cudaGetSymbolAddress((void**)&OT,  g_OUT);
    cudaGetSymbolAddress((void**)&G,   g_G);
    cudaGetSymbolAddress((void**)&DBETA, g_DBETA);
    cudaGetSymbolAddress((void**)&AH,  g_AH);
    cudaGetSymbolAddress((void**)&AL,  g_AL);
    cudaGetSymbolAddress((void**)&CNh, g_CNh);
    cudaGetSymbolAddress((void**)&CNl, g_CNl);
    cudaGetSymbolAddress((void**)&WtH, g_WtH);
    cudaGetSymbolAddress((void**)&WtL, g_WtL);
    cudaGetSymbolAddress((void**)&WoH, g_WoH);
    cudaGetSymbolAddress((void**)&WoL, g_WoL);
    cudaGetSymbolAddress((void**)&WgH, g_WgH);
    cudaGetSymbolAddress((void**)&WgL, g_WgL);

    init_decay_kernel<<<4, 256>>>();

    // weight splits
    split_kernel<<<(DH * DH / 4 + 255) / 256, 256>>>(Wt, WtH, WtL, DH * DH / 4);
    split_kernel<<<(DH * DH / 4 + 255) / 256, 256>>>(Wo, WoH, WoL, DH * DH / 4);
    split_kernel<<<(2 * DH * DH / 4 + 255) / 256, 256>>>(Wg, WgH, WgL, 2 * DH * DH / 4);

    // _x = LN(x): fp32 residual + hi/lo into concat buffer cols [0,1024)
    ln_kernel<<<MM, 256>>>(x, ln1_w, ln1_b, XN, AH, AL, 2 * DH);

    dim3 ggrid(DH / 128, MM / 128);  // (8, 128)

    // u = (_x @ Wt) * decay_beta
    gemm_split_kernel<<<ggrid, 256>>>(AH, AL, 2 * DH, WtH, WtL, DH,
                                      U, DBETA, nullptr,
                                      nullptr, nullptr, 0, 0);

    // cx = decay scan (in place on U)
    scan_kernel<<<(BB * DH) / 128, 128>>>(U);

    // LN(cx) -> hi/lo only
    ln_kernel<<<MM, 256>>>(U, lnc_w, lnc_b, nullptr, CNh, CNl, DH);

    // out = LN(cx) @ Wo : fp32 OT + hi/lo into concat buffer cols [1024,2048)
    gemm_split_kernel<<<ggrid, 256>>>(CNh, CNl, DH, WoH, WoL, DH,
                                      OT, nullptr, nullptr,
                                      AH, AL, 2 * DH, DH);

    // g = concat(_x, out) @ Wg + bg   (K = 2048, concat buffer is contiguous)
    gemm_split_kernel<<<ggrid, 256>>>(AH, AL, 2 * DH, WgH, WgL, 2 * DH,
                                      G, nullptr, bg,
                                      nullptr, nullptr, 0, 0);

    // y = (1-sigmoid(LN(g))) * _x + sigmoid(LN(g)) * out
    gate_kernel<<<MM, 256>>>(G, XN, OT, lng_w, lng_b, out);
}